// round 4
// baseline (speedup 1.0000x reference)
#include <cuda_runtime.h>
#include <cuda_bf16.h>

// RandomForest: x[8192,256] f32, node_w[100,31,256], node_b[100,31], leaves[100,32,64]
// out[8192,64] = mean over trees of leaves[t, leaf_idx(t,s)]
//
// Key facts:
//  - decision: sigmoid(z) <= 0.5  <=>  z <= 0
//  - idx recurrence starts at 0 => only node indices 0..15 are ever used
//
// One fused kernel: 16 warps/block = 16 samples/block, 512 blocks.
// Per block loop over 100 trees with double-buffered smem staging of the
// 16 live node rows (16KB contiguous) + biases. Warp = one sample, x row in
// registers, 5 warp-cooperative dots per tree, butterfly reduce (bitwise
// uniform across lanes -> uniform idx, no divergence), coalesced leaf gather.

#define NUM_TREES   100
#define TREE_DEPTH  5
#define DIM         256
#define NCLS        64
#define NODE_STRIDE 31          // node_w row stride per tree (31 nodes stored)
#define USED_NODES  16          // only nodes 0..15 are reachable
#define NLEAVES     32
#define BATCH       8192

#define WARPS_PER_BLOCK 16
#define THREADS (WARPS_PER_BLOCK * 32)
#define W_F4_PER_STAGE (USED_NODES * DIM / 4)   // 1024 float4 per tree stage

__global__ __launch_bounds__(THREADS)
void forest_kernel(const float* __restrict__ x,
                   const float* __restrict__ node_w,
                   const float* __restrict__ node_b,
                   const float* __restrict__ leaves,
                   float* __restrict__ out)
{
    __shared__ float ws[2][USED_NODES * DIM];   // 2 x 16KB
    __shared__ float bs[2][USED_NODES];

    const int tid  = threadIdx.x;
    const int warp = tid >> 5;
    const int lane = tid & 31;
    const int s    = blockIdx.x * WARPS_PER_BLOCK + warp;   // sample id, < 8192

    // x row in registers: lane holds x[s][lane*4 .. +3] and x[s][128+lane*4 .. +3]
    const float4* xr4 = reinterpret_cast<const float4*>(x + (size_t)s * DIM);
    const float4 xa = xr4[lane];
    const float4 xb = xr4[lane + 32];

    float acc0 = 0.0f, acc1 = 0.0f;

    // ---- prime stage: tree 0 into buffer 0 ----
    {
        const float4* wsrc = reinterpret_cast<const float4*>(node_w);
        float4* wdst = reinterpret_cast<float4*>(ws[0]);
        wdst[tid]           = wsrc[tid];
        wdst[tid + THREADS] = wsrc[tid + THREADS];
        if (tid < USED_NODES) bs[0][tid] = node_b[tid];
    }
    __syncthreads();

    for (int t = 0; t < NUM_TREES; ++t) {
        const int cur = t & 1;

        // prefetch next tree's live nodes through registers (hidden by compute)
        float4 p0, p1;
        float  pb = 0.0f;
        const bool has_next = (t + 1 < NUM_TREES);
        if (has_next) {
            const float4* wsrc = reinterpret_cast<const float4*>(
                node_w + (size_t)(t + 1) * NODE_STRIDE * DIM);
            p0 = wsrc[tid];
            p1 = wsrc[tid + THREADS];
            if (tid < USED_NODES) pb = node_b[(t + 1) * NODE_STRIDE + tid];
        }

        // ---- traversal: 5 levels, warp-cooperative dot per level ----
        const float* w = ws[cur];
        int idx = 0;
        #pragma unroll
        for (int l = 0; l < TREE_DEPTH; ++l) {
            const float4* wrow = reinterpret_cast<const float4*>(w + idx * DIM);
            const float4 wa = wrow[lane];        // conflict-free LDS.128
            const float4 wb = wrow[lane + 32];
            float p = wa.x * xa.x + wa.y * xa.y + wa.z * xa.z + wa.w * xa.w
                    + wb.x * xb.x + wb.y * xb.y + wb.z * xb.z + wb.w * xb.w;
            #pragma unroll
            for (int o = 16; o > 0; o >>= 1)
                p += __shfl_xor_sync(0xffffffffu, p, o);
            const float z = p + bs[cur][idx];
            idx = 2 * idx + (z <= 0.0f ? 1 : 0);   // uniform across warp
        }

        // ---- leaf accumulate (coalesced 2x128B from L2-resident leaves) ----
        const float* lv = leaves + ((size_t)t * NLEAVES + idx) * NCLS;
        acc0 += lv[lane];
        acc1 += lv[lane + 32];

        // ---- commit prefetched stage, one barrier per tree ----
        if (has_next) {
            float4* wdst = reinterpret_cast<float4*>(ws[cur ^ 1]);
            wdst[tid]           = p0;
            wdst[tid + THREADS] = p1;
            if (tid < USED_NODES) bs[cur ^ 1][tid] = pb;
            __syncthreads();
        }
    }

    const float inv = 1.0f / (float)NUM_TREES;
    out[(size_t)s * NCLS + lane]      = acc0 * inv;
    out[(size_t)s * NCLS + lane + 32] = acc1 * inv;
}

extern "C" void kernel_launch(void* const* d_in, const int* in_sizes, int n_in,
                              void* d_out, int out_size)
{
    const float* x      = (const float*)d_in[0];
    const float* node_w = (const float*)d_in[1];
    const float* node_b = (const float*)d_in[2];
    const float* leaves = (const float*)d_in[3];
    float* out = (float*)d_out;

    const int blocks = BATCH / WARPS_PER_BLOCK;   // 512
    forest_kernel<<<blocks, THREADS>>>(x, node_w, node_b, leaves, out);
}

// round 6
// speedup vs baseline: 2.8517x; 2.8517x over previous
#include <cuda_runtime.h>
#include <cuda_fp16.h>
#include <cstdint>

// RandomForest via warp-level tensor cores (mma.sync, arch-neutral for sm_103):
//   Z[8192,1600] = X[8192,256] . W_used[1600,256]^T + b   (100 trees x 16 live nodes)
//   fp16 1-pass GEMM -> sign bits + near-zero flags (tau = 11 sigma of fp16 error)
//   traversal kernel: bit-walk, fp32 warp-dot recheck for flagged nodes, leaf gather.

#define NUM_TREES   100
#define DIM         256
#define NCLS        64
#define NODE_STRIDE 31
#define USED_NODES  16
#define NLEAVES     32
#define BATCH       8192

#define MTILE   128
#define NTILE   64
#define NGROUPS 25            // 1600 node-columns / 64
#define NLIVE   (NUM_TREES * USED_NODES)   // 1600
#define TAU     0.05f

// ---- device-global scratch (no allocs) ----
__device__ __half g_xh[(size_t)BATCH * DIM];        // fp16 X
__device__ __half g_wh[(size_t)NLIVE * DIM];        // fp16 live W rows, [tree*16+node][k]
__device__ unsigned long long g_signs[(size_t)BATCH * NGROUPS];
__device__ unsigned long long g_flags[(size_t)BATCH * NGROUPS];

// ---- smem layout for GEMM (halves, row stride 264 = 256 + 8 pad) ----
#define LDS_STRIDE 264
#define AS_OFF  0                                   // 128*264*2 = 67584 B
#define BS_OFF  67584                               // 64*264*2  = 33792 B
#define BIAS_OFF 101376                             // 64*4 = 256 B
#define SMEM_G   101632
#define ZSTRIDE 66                                  // zbuf overlays AS region

__device__ __forceinline__ uint32_t smem_u32(const void* p) {
    uint32_t a;
    asm("{ .reg .u64 t; cvta.to.shared.u64 t, %1; cvt.u32.u64 %0, t; }" : "=r"(a) : "l"(p));
    return a;
}
__device__ __forceinline__ void ldsm4(uint32_t* r, uint32_t addr) {
    asm volatile("ldmatrix.sync.aligned.m8n8.x4.shared.b16 {%0,%1,%2,%3}, [%4];"
                 : "=r"(r[0]), "=r"(r[1]), "=r"(r[2]), "=r"(r[3]) : "r"(addr));
}
__device__ __forceinline__ void mma16816(float* c, const uint32_t* a, uint32_t b0, uint32_t b1) {
    asm volatile(
        "mma.sync.aligned.m16n8k16.row.col.f32.f16.f16.f32 "
        "{%0,%1,%2,%3}, {%4,%5,%6,%7}, {%8,%9}, {%0,%1,%2,%3};"
        : "+f"(c[0]), "+f"(c[1]), "+f"(c[2]), "+f"(c[3])
        : "r"(a[0]), "r"(a[1]), "r"(a[2]), "r"(a[3]), "r"(b0), "r"(b1));
}

// ================= fp32 -> fp16 preconvert =================
#define XQ (BATCH * DIM / 4)          // 524288 float4-quads for X
#define WQ (NLIVE * DIM / 4)          // 102400 quads for W
__global__ __launch_bounds__(256)
void convert_kernel(const float* __restrict__ x, const float* __restrict__ node_w)
{
    const int i = blockIdx.x * 256 + threadIdx.x;
    if (i < XQ) {
        const float4 v = ((const float4*)x)[i];
        __half2 h0 = __floats2half2_rn(v.x, v.y);
        __half2 h1 = __floats2half2_rn(v.z, v.w);
        uint2 r = { *(uint32_t*)&h0, *(uint32_t*)&h1 };
        ((uint2*)g_xh)[i] = r;
    } else {
        const int j = i - XQ;
        if (j < WQ) {
            const int n  = j >> 6;            // live row 0..1599: tree*16+node
            const int k4 = (j & 63) * 4;
            const int tree = n >> 4, node = n & 15;
            const float4 v = *(const float4*)(node_w
                + ((size_t)tree * NODE_STRIDE + node) * DIM + k4);
            __half2 h0 = __floats2half2_rn(v.x, v.y);
            __half2 h1 = __floats2half2_rn(v.z, v.w);
            uint2 r = { *(uint32_t*)&h0, *(uint32_t*)&h1 };
            ((uint2*)g_wh)[j] = r;
        }
    }
}

// ================= GEMM + sign/flag epilogue =================
// grid (25, 64): x = node-column tile, y = sample tile. 256 threads, 2 CTA/SM.
__global__ __launch_bounds__(256)
void forest_gemm_kernel(const float* __restrict__ node_b)
{
    extern __shared__ char sm[];
    __half* As = (__half*)(sm + AS_OFF);
    __half* Bs = (__half*)(sm + BS_OFF);
    float* bias = (float*)(sm + BIAS_OFF);
    const uint32_t sbase = smem_u32(sm);

    const int tid    = threadIdx.x;
    const int wid    = tid >> 5;
    const int lane   = tid & 31;
    const int tile_n = blockIdx.x;
    const int m0     = blockIdx.y * MTILE;

    if (tid < NTILE) {
        const int tr = tile_n * 4 + (tid >> 4);
        bias[tid] = node_b[tr * NODE_STRIDE + (tid & 15)];
    }

    // stage A [128 x 256]h and B [64 x 256]h, coalesced 16B loads
    #pragma unroll
    for (int it = 0; it < 16; ++it) {
        const int idx = tid + it * 256;
        const int r = idx >> 5, c8 = (idx & 31) * 8;
        const uint4 v = *(const uint4*)(g_xh + (size_t)(m0 + r) * DIM + c8);
        *(uint4*)(As + r * LDS_STRIDE + c8) = v;
    }
    #pragma unroll
    for (int it = 0; it < 8; ++it) {
        const int idx = tid + it * 256;
        const int r = idx >> 5, c8 = (idx & 31) * 8;
        const uint4 v = *(const uint4*)(g_wh + (size_t)(tile_n * NTILE + r) * DIM + c8);
        *(uint4*)(Bs + r * LDS_STRIDE + c8) = v;
    }
    __syncthreads();

    // warp tiles: wm in 0..3 (rows wm*32), wn in 0..1 (cols wn*32)
    const int wm = wid >> 1, wn = wid & 1;
    float acc[2][4][4];
    #pragma unroll
    for (int i = 0; i < 2; ++i)
        #pragma unroll
        for (int j = 0; j < 4; ++j)
            #pragma unroll
            for (int q = 0; q < 4; ++q) acc[i][j][q] = 0.0f;

    // per-lane ldmatrix base addresses
    uint32_t aaddr[2], baddr[2];
    #pragma unroll
    for (int i = 0; i < 2; ++i) {
        const int row = wm * 32 + i * 16 + (lane & 15);
        const int hc  = (lane >> 4) * 8;
        aaddr[i] = sbase + AS_OFF + (uint32_t)(row * LDS_STRIDE + hc) * 2;
    }
    #pragma unroll
    for (int j = 0; j < 2; ++j) {
        const int row = wn * 32 + j * 16 + (lane & 7) + ((lane >> 4) & 1) * 8;
        const int hc  = ((lane >> 3) & 1) * 8;
        baddr[j] = sbase + BS_OFF + (uint32_t)(row * LDS_STRIDE + hc) * 2;
    }

    #pragma unroll
    for (int ks = 0; ks < 16; ++ks) {
        const uint32_t koff = (uint32_t)ks * 32;   // 16 halves
        uint32_t a[2][4], b[2][4];
        ldsm4(a[0], aaddr[0] + koff);
        ldsm4(a[1], aaddr[1] + koff);
        ldsm4(b[0], baddr[0] + koff);
        ldsm4(b[1], baddr[1] + koff);
        #pragma unroll
        for (int i = 0; i < 2; ++i)
            #pragma unroll
            for (int j = 0; j < 2; ++j) {
                mma16816(acc[i][2 * j],     a[i], b[j][0], b[j][1]);
                mma16816(acc[i][2 * j + 1], a[i], b[j][2], b[j][3]);
            }
    }
    __syncthreads();   // all warps done reading As before zbuf overlay

    // scatter accum -> zbuf[128][66] (overlays As)
    float* zbuf = (float*)(sm + AS_OFF);
    const int g = lane >> 2, t = lane & 3;
    #pragma unroll
    for (int i = 0; i < 2; ++i)
        #pragma unroll
        for (int jj = 0; jj < 4; ++jj) {
            const int row0 = wm * 32 + i * 16 + g;
            const int col0 = wn * 32 + jj * 8 + t * 2;
            *(float2*)&zbuf[row0 * ZSTRIDE + col0]       = make_float2(acc[i][jj][0], acc[i][jj][1]);
            *(float2*)&zbuf[(row0 + 8) * ZSTRIDE + col0] = make_float2(acc[i][jj][2], acc[i][jj][3]);
        }
    __syncthreads();

    // pack one row per thread: 64 z-values -> sign/flag u64 masks
    if (tid < MTILE) {
        unsigned long long sg = 0ull, fl = 0ull;
        #pragma unroll
        for (int c = 0; c < 64; ++c) {
            const float z = zbuf[tid * ZSTRIDE + c] + bias[c];
            if (z <= 0.0f)      sg |= 1ull << c;
            if (fabsf(z) < TAU) fl |= 1ull << c;
        }
        g_signs[(size_t)(m0 + tid) * NGROUPS + tile_n] = sg;
        g_flags[(size_t)(m0 + tid) * NGROUPS + tile_n] = fl;
    }
}

// ================= traversal + leaf gather =================
#define T_WARPS 16
#define T_THREADS (T_WARPS * 32)

__global__ __launch_bounds__(T_THREADS)
void forest_traverse_kernel(const float* __restrict__ x,
                            const float* __restrict__ node_w,
                            const float* __restrict__ node_b,
                            const float* __restrict__ leaves,
                            float* __restrict__ out)
{
    __shared__ unsigned long long sgb[T_WARPS][NGROUPS];
    __shared__ unsigned long long flb[T_WARPS][NGROUPS];

    const int tid  = threadIdx.x;
    const int warp = tid >> 5;
    const int lane = tid & 31;
    const int s    = blockIdx.x * T_WARPS + warp;

    // x row in registers (only for rare fp32 rechecks)
    const float4* xr4 = reinterpret_cast<const float4*>(x + (size_t)s * DIM);
    const float4 xa = xr4[lane];
    const float4 xb = xr4[lane + 32];

    if (lane < NGROUPS) {
        sgb[warp][lane] = g_signs[(size_t)s * NGROUPS + lane];
        flb[warp][lane] = g_flags[(size_t)s * NGROUPS + lane];
    }
    __syncwarp();

    float acc0 = 0.0f, acc1 = 0.0f;

    auto walk = [&](int t) -> int {
        const uint32_t sh = (uint32_t)((t & 3) << 4);
        const uint32_t sW = (uint32_t)(sgb[warp][t >> 2] >> sh) & 0xFFFFu;
        const uint32_t fW = (uint32_t)(flb[warp][t >> 2] >> sh) & 0xFFFFu;
        int idx = 0;
        #pragma unroll
        for (int l = 0; l < 5; ++l) {
            int bit;
            if ((fW >> idx) & 1u) {
                // exact fp32 recheck — identical arithmetic to the R0 SIMT kernel
                const float4* wr = reinterpret_cast<const float4*>(
                    node_w + ((size_t)t * NODE_STRIDE + idx) * DIM);
                const float4 wa = wr[lane];
                const float4 wb = wr[lane + 32];
                float p = wa.x * xa.x + wa.y * xa.y + wa.z * xa.z + wa.w * xa.w
                        + wb.x * xb.x + wb.y * xb.y + wb.z * xb.z + wb.w * xb.w;
                #pragma unroll
                for (int o = 16; o > 0; o >>= 1)
                    p += __shfl_xor_sync(0xffffffffu, p, o);
                const float z = p + node_b[t * NODE_STRIDE + idx];
                bit = (z <= 0.0f) ? 1 : 0;
            } else {
                bit = (int)((sW >> idx) & 1u);
            }
            idx = 2 * idx + bit;
        }
        return idx;
    };

    // 1-deep leaf prefetch pipeline
    int idx0 = walk(0);
    const float* lv = leaves + (size_t)idx0 * NCLS;
    float v0 = lv[lane];
    float v1 = lv[lane + 32];

    for (int t = 1; t < NUM_TREES; ++t) {
        const int idx = walk(t);
        const float* lvt = leaves + ((size_t)t * NLEAVES + idx) * NCLS;
        const float n0 = lvt[lane];
        const float n1 = lvt[lane + 32];
        acc0 += v0; acc1 += v1;
        v0 = n0; v1 = n1;
    }
    acc0 += v0; acc1 += v1;

    const float inv = 1.0f / (float)NUM_TREES;
    out[(size_t)s * NCLS + lane]      = acc0 * inv;
    out[(size_t)s * NCLS + lane + 32] = acc1 * inv;
}

extern "C" void kernel_launch(void* const* d_in, const int* in_sizes, int n_in,
                              void* d_out, int out_size)
{
    const float* x      = (const float*)d_in[0];
    const float* node_w = (const float*)d_in[1];
    const float* node_b = (const float*)d_in[2];
    const float* leaves = (const float*)d_in[3];
    float* out = (float*)d_out;

    cudaFuncSetAttribute(forest_gemm_kernel,
                         cudaFuncAttributeMaxDynamicSharedMemorySize, SMEM_G);

    convert_kernel<<<(XQ + WQ + 255) / 256, 256>>>(x, node_w);
    forest_gemm_kernel<<<dim3(NGROUPS, BATCH / MTILE), 256, SMEM_G>>>(node_b);
    forest_traverse_kernel<<<BATCH / T_WARPS, T_THREADS>>>(x, node_w, node_b, leaves, out);
}

// round 7
// speedup vs baseline: 4.5321x; 1.5892x over previous
#include <cuda_runtime.h>
#include <cuda_fp16.h>
#include <cstdint>

// RandomForest via warp-level tensor cores (mma.sync, arch-neutral for sm_103):
//   Z[8192,1600] = X[8192,256] . W_used[1600,256]^T + b   (100 trees x 16 live nodes)
//   fp16 1-pass GEMM -> sign bits + near-zero flags (tau ~= 11 sigma of fp16 error)
//   traversal: lane-parallel bit-walks + rare fp32 warp-dot recheck,
//              then deep-pipelined fp16 leaf gather.

#define NUM_TREES   100
#define DIM         256
#define NCLS        64
#define NODE_STRIDE 31
#define USED_NODES  16
#define NLEAVES     32
#define BATCH       8192

#define MTILE   128
#define NTILE   64
#define NGROUPS 25            // 1600 node-columns / 64
#define NLIVE   (NUM_TREES * USED_NODES)   // 1600
#define TAU     0.05f

// ---- device-global scratch (no allocs) ----
__device__ __half g_xh[(size_t)BATCH * DIM];        // fp16 X
__device__ __half g_wh[(size_t)NLIVE * DIM];        // fp16 live W rows
__device__ __half g_lh[(size_t)NUM_TREES * NLEAVES * NCLS];   // fp16 leaves
__device__ unsigned long long g_signs[(size_t)BATCH * NGROUPS];
__device__ unsigned long long g_flags[(size_t)BATCH * NGROUPS];

// ---- smem layout for GEMM (halves, row stride 264 = 256 + 8 pad) ----
#define LDS_STRIDE 264
#define AS_OFF  0                                   // 128*264*2 = 67584 B
#define BS_OFF  67584                               // 64*264*2  = 33792 B
#define BIAS_OFF 101376                             // 64*4 = 256 B
#define SMEM_G   101632
#define ZSTRIDE 66                                  // zbuf overlays AS region

__device__ __forceinline__ uint32_t smem_u32(const void* p) {
    uint32_t a;
    asm("{ .reg .u64 t; cvta.to.shared.u64 t, %1; cvt.u32.u64 %0, t; }" : "=r"(a) : "l"(p));
    return a;
}
__device__ __forceinline__ void ldsm4(uint32_t* r, uint32_t addr) {
    asm volatile("ldmatrix.sync.aligned.m8n8.x4.shared.b16 {%0,%1,%2,%3}, [%4];"
                 : "=r"(r[0]), "=r"(r[1]), "=r"(r[2]), "=r"(r[3]) : "r"(addr));
}
__device__ __forceinline__ void mma16816(float* c, const uint32_t* a, uint32_t b0, uint32_t b1) {
    asm volatile(
        "mma.sync.aligned.m16n8k16.row.col.f32.f16.f16.f32 "
        "{%0,%1,%2,%3}, {%4,%5,%6,%7}, {%8,%9}, {%0,%1,%2,%3};"
        : "+f"(c[0]), "+f"(c[1]), "+f"(c[2]), "+f"(c[3])
        : "r"(a[0]), "r"(a[1]), "r"(a[2]), "r"(a[3]), "r"(b0), "r"(b1));
}

// ================= fp32 -> fp16 preconvert (X, live W rows, leaves) ============
#define XQ (BATCH * DIM / 4)                    // 524288
#define WQ (NLIVE * DIM / 4)                    // 102400
#define LQ (NUM_TREES * NLEAVES * NCLS / 4)     // 51200
__global__ __launch_bounds__(256)
void convert_kernel(const float* __restrict__ x, const float* __restrict__ node_w,
                    const float* __restrict__ leaves)
{
    const int i = blockIdx.x * 256 + threadIdx.x;
    float4 v;
    uint2* dst;
    if (i < XQ) {
        v = ((const float4*)x)[i];
        dst = ((uint2*)g_xh) + i;
    } else if (i < XQ + WQ) {
        const int j = i - XQ;
        const int n  = j >> 6;            // live row 0..1599: tree*16+node
        const int k4 = (j & 63) * 4;
        const int tree = n >> 4, node = n & 15;
        v = *(const float4*)(node_w + ((size_t)tree * NODE_STRIDE + node) * DIM + k4);
        dst = ((uint2*)g_wh) + j;
    } else if (i < XQ + WQ + LQ) {
        const int j = i - XQ - WQ;
        v = ((const float4*)leaves)[j];
        dst = ((uint2*)g_lh) + j;
    } else {
        return;
    }
    __half2 h0 = __floats2half2_rn(v.x, v.y);
    __half2 h1 = __floats2half2_rn(v.z, v.w);
    uint2 r = { *(uint32_t*)&h0, *(uint32_t*)&h1 };
    *dst = r;
}

// ================= GEMM + sign/flag epilogue =================
// grid (25, 64): x = node-column tile, y = sample tile. 256 threads, 2 CTA/SM.
__global__ __launch_bounds__(256)
void forest_gemm_kernel(const float* __restrict__ node_b)
{
    extern __shared__ char sm[];
    __half* As = (__half*)(sm + AS_OFF);
    __half* Bs = (__half*)(sm + BS_OFF);
    float* bias = (float*)(sm + BIAS_OFF);
    const uint32_t sbase = smem_u32(sm);

    const int tid    = threadIdx.x;
    const int wid    = tid >> 5;
    const int lane   = tid & 31;
    const int tile_n = blockIdx.x;
    const int m0     = blockIdx.y * MTILE;

    if (tid < NTILE) {
        const int tr = tile_n * 4 + (tid >> 4);
        bias[tid] = node_b[tr * NODE_STRIDE + (tid & 15)];
    }

    // stage A [128 x 256]h and B [64 x 256]h, coalesced 16B loads
    #pragma unroll
    for (int it = 0; it < 16; ++it) {
        const int idx = tid + it * 256;
        const int r = idx >> 5, c8 = (idx & 31) * 8;
        const uint4 v = *(const uint4*)(g_xh + (size_t)(m0 + r) * DIM + c8);
        *(uint4*)(As + r * LDS_STRIDE + c8) = v;
    }
    #pragma unroll
    for (int it = 0; it < 8; ++it) {
        const int idx = tid + it * 256;
        const int r = idx >> 5, c8 = (idx & 31) * 8;
        const uint4 v = *(const uint4*)(g_wh + (size_t)(tile_n * NTILE + r) * DIM + c8);
        *(uint4*)(Bs + r * LDS_STRIDE + c8) = v;
    }
    __syncthreads();

    // warp tiles: wm in 0..3 (rows wm*32), wn in 0..1 (cols wn*32)
    const int wm = wid >> 1, wn = wid & 1;
    float acc[2][4][4];
    #pragma unroll
    for (int i = 0; i < 2; ++i)
        #pragma unroll
        for (int j = 0; j < 4; ++j)
            #pragma unroll
            for (int q = 0; q < 4; ++q) acc[i][j][q] = 0.0f;

    // per-lane ldmatrix base addresses
    uint32_t aaddr[2], baddr[2];
    #pragma unroll
    for (int i = 0; i < 2; ++i) {
        const int row = wm * 32 + i * 16 + (lane & 15);
        const int hc  = (lane >> 4) * 8;
        aaddr[i] = sbase + AS_OFF + (uint32_t)(row * LDS_STRIDE + hc) * 2;
    }
    #pragma unroll
    for (int j = 0; j < 2; ++j) {
        const int row = wn * 32 + j * 16 + (lane & 7) + ((lane >> 4) & 1) * 8;
        const int hc  = ((lane >> 3) & 1) * 8;
        baddr[j] = sbase + BS_OFF + (uint32_t)(row * LDS_STRIDE + hc) * 2;
    }

    #pragma unroll
    for (int ks = 0; ks < 16; ++ks) {
        const uint32_t koff = (uint32_t)ks * 32;   // 16 halves
        uint32_t a[2][4], b[2][4];
        ldsm4(a[0], aaddr[0] + koff);
        ldsm4(a[1], aaddr[1] + koff);
        ldsm4(b[0], baddr[0] + koff);
        ldsm4(b[1], baddr[1] + koff);
        #pragma unroll
        for (int i = 0; i < 2; ++i)
            #pragma unroll
            for (int j = 0; j < 2; ++j) {
                mma16816(acc[i][2 * j],     a[i], b[j][0], b[j][1]);
                mma16816(acc[i][2 * j + 1], a[i], b[j][2], b[j][3]);
            }
    }
    __syncthreads();   // all warps done reading As before zbuf overlay

    // scatter accum -> zbuf[128][66] (overlays As)
    float* zbuf = (float*)(sm + AS_OFF);
    const int g = lane >> 2, t = lane & 3;
    #pragma unroll
    for (int i = 0; i < 2; ++i)
        #pragma unroll
        for (int jj = 0; jj < 4; ++jj) {
            const int row0 = wm * 32 + i * 16 + g;
            const int col0 = wn * 32 + jj * 8 + t * 2;
            *(float2*)&zbuf[row0 * ZSTRIDE + col0]       = make_float2(acc[i][jj][0], acc[i][jj][1]);
            *(float2*)&zbuf[(row0 + 8) * ZSTRIDE + col0] = make_float2(acc[i][jj][2], acc[i][jj][3]);
        }
    __syncthreads();

    // pack one row per thread: 64 z-values -> sign/flag u64 masks
    if (tid < MTILE) {
        unsigned long long sg = 0ull, fl = 0ull;
        #pragma unroll
        for (int c = 0; c < 64; ++c) {
            const float z = zbuf[tid * ZSTRIDE + c] + bias[c];
            if (z <= 0.0f)      sg |= 1ull << c;
            if (fabsf(z) < TAU) fl |= 1ull << c;
        }
        g_signs[(size_t)(m0 + tid) * NGROUPS + tile_n] = sg;
        g_flags[(size_t)(m0 + tid) * NGROUPS + tile_n] = fl;
    }
}

// ================= traversal + leaf gather =================
#define T_WARPS 16
#define T_THREADS (T_WARPS * 32)

__global__ __launch_bounds__(T_THREADS)
void forest_traverse_kernel(const float* __restrict__ x,
                            const float* __restrict__ node_w,
                            const float* __restrict__ node_b,
                            float* __restrict__ out)
{
    __shared__ unsigned long long sgb[T_WARPS][NGROUPS];
    __shared__ unsigned long long flb[T_WARPS][NGROUPS];
    __shared__ uint8_t sidx[T_WARPS][104];

    const int tid  = threadIdx.x;
    const int warp = tid >> 5;
    const int lane = tid & 31;
    const int s    = blockIdx.x * T_WARPS + warp;

    // x row in registers (only for rare fp32 rechecks)
    const float4* xr4 = reinterpret_cast<const float4*>(x + (size_t)s * DIM);
    const float4 xa = xr4[lane];
    const float4 xb = xr4[lane + 32];

    if (lane < NGROUPS) {
        sgb[warp][lane] = g_signs[(size_t)s * NGROUPS + lane];
        flb[warp][lane] = g_flags[(size_t)s * NGROUPS + lane];
    }
    __syncwarp();

    // ---- phase 1: lane-parallel bit walks; collect tainted trees ----
    uint32_t tb[4];
    #pragma unroll
    for (int r = 0; r < 4; ++r) {
        const int t = r * 32 + lane;
        int taint = 0;
        if (t < NUM_TREES) {
            const uint32_t sh = (uint32_t)((t & 3) << 4);
            const uint32_t sW = (uint32_t)(sgb[warp][t >> 2] >> sh) & 0xFFFFu;
            const uint32_t fW = (uint32_t)(flb[warp][t >> 2] >> sh) & 0xFFFFu;
            int idx = 0;
            #pragma unroll
            for (int l = 0; l < 5; ++l) {
                taint |= (int)((fW >> idx) & 1u);
                idx = 2 * idx + (int)((sW >> idx) & 1u);
            }
            sidx[warp][t] = (uint8_t)idx;
        }
        tb[r] = __ballot_sync(0xffffffffu, taint != 0);
    }

    // ---- phase 2: warp-cooperative re-walk of tainted trees (rare) ----
    #pragma unroll
    for (int r = 0; r < 4; ++r) {
        uint32_t m = tb[r];
        while (m) {
            const int l = __ffs(m) - 1;
            m &= m - 1u;
            const int t = r * 32 + l;
            const uint32_t sh = (uint32_t)((t & 3) << 4);
            const uint32_t sW = (uint32_t)(sgb[warp][t >> 2] >> sh) & 0xFFFFu;
            const uint32_t fW = (uint32_t)(flb[warp][t >> 2] >> sh) & 0xFFFFu;
            int idx = 0;
            #pragma unroll
            for (int lv = 0; lv < 5; ++lv) {
                int bit;
                if ((fW >> idx) & 1u) {
                    // exact fp32 recheck — identical arithmetic to the R0 SIMT kernel
                    const float4* wr = reinterpret_cast<const float4*>(
                        node_w + ((size_t)t * NODE_STRIDE + idx) * DIM);
                    const float4 wa = wr[lane];
                    const float4 wb = wr[lane + 32];
                    float p = wa.x * xa.x + wa.y * xa.y + wa.z * xa.z + wa.w * xa.w
                            + wb.x * xb.x + wb.y * xb.y + wb.z * xb.z + wb.w * xb.w;
                    #pragma unroll
                    for (int o = 16; o > 0; o >>= 1)
                        p += __shfl_xor_sync(0xffffffffu, p, o);
                    const float z = p + node_b[t * NODE_STRIDE + idx];
                    bit = (z <= 0.0f) ? 1 : 0;
                } else {
                    bit = (int)((sW >> idx) & 1u);
                }
                idx = 2 * idx + bit;
            }
            if (lane == 0) sidx[warp][t] = (uint8_t)idx;
        }
    }
    __syncwarp();

    // ---- phase 3: deep-pipelined fp16 leaf gather ----
    // lane owns classes (2*lane, 2*lane+1): one u32 (half2) per tree per lane.
    const __half* lbase = g_lh + 2 * lane;
    float accx = 0.0f, accy = 0.0f;

    uint32_t pv[4];
    {
        const uchar4 i4 = *(const uchar4*)&sidx[warp][0];
        pv[0] = *(const uint32_t*)(lbase + ((size_t)(0 * NLEAVES) + i4.x) * NCLS);
        pv[1] = *(const uint32_t*)(lbase + ((size_t)(1 * NLEAVES) + i4.y) * NCLS);
        pv[2] = *(const uint32_t*)(lbase + ((size_t)(2 * NLEAVES) + i4.z) * NCLS);
        pv[3] = *(const uint32_t*)(lbase + ((size_t)(3 * NLEAVES) + i4.w) * NCLS);
    }
    #pragma unroll
    for (int gq = 0; gq < 25; ++gq) {
        uint32_t nv[4];
        if (gq < 24) {
            const int t0 = (gq + 1) * 4;
            const uchar4 i4 = *(const uchar4*)&sidx[warp][t0];
            nv[0] = *(const uint32_t*)(lbase + ((size_t)((t0 + 0) * NLEAVES) + i4.x) * NCLS);
            nv[1] = *(const uint32_t*)(lbase + ((size_t)((t0 + 1) * NLEAVES) + i4.y) * NCLS);
            nv[2] = *(const uint32_t*)(lbase + ((size_t)((t0 + 2) * NLEAVES) + i4.z) * NCLS);
            nv[3] = *(const uint32_t*)(lbase + ((size_t)((t0 + 3) * NLEAVES) + i4.w) * NCLS);
        }
        #pragma unroll
        for (int q = 0; q < 4; ++q) {
            const float2 f = __half22float2(*(__half2*)&pv[q]);
            accx += f.x;
            accy += f.y;
        }
        if (gq < 24) { pv[0] = nv[0]; pv[1] = nv[1]; pv[2] = nv[2]; pv[3] = nv[3]; }
    }

    const float inv = 1.0f / (float)NUM_TREES;
    *(float2*)(out + (size_t)s * NCLS + 2 * lane) = make_float2(accx * inv, accy * inv);
}

extern "C" void kernel_launch(void* const* d_in, const int* in_sizes, int n_in,
                              void* d_out, int out_size)
{
    const float* x      = (const float*)d_in[0];
    const float* node_w = (const float*)d_in[1];
    const float* node_b = (const float*)d_in[2];
    const float* leaves = (const float*)d_in[3];
    float* out = (float*)d_out;

    cudaFuncSetAttribute(forest_gemm_kernel,
                         cudaFuncAttributeMaxDynamicSharedMemorySize, SMEM_G);

    convert_kernel<<<(XQ + WQ + LQ + 255) / 256, 256>>>(x, node_w, leaves);
    forest_gemm_kernel<<<dim3(NGROUPS, BATCH / MTILE), 256, SMEM_G>>>(node_b);
    forest_traverse_kernel<<<BATCH / T_WARPS, T_THREADS>>>(x, node_w, node_b, out);
}